// round 5
// baseline (speedup 1.0000x reference)
#include <cuda_runtime.h>
#include <cuda_fp16.h>
#include <cuda_bf16.h>

#define MAX_N 50000
#define MAX_E 600000
#define D 128

// scratch (no allocation allowed -> __device__ globals)
__device__ __half g_h1[MAX_N * D];
__device__ float  g_agg1[MAX_N * D];
__device__ __half g_h2[MAX_N * D];
__device__ float  g_deg[MAX_N];
__device__ float  g_dis[MAX_N];
__device__ int    g_cnt[MAX_N];
__device__ int    g_cnt2[MAX_N];
__device__ int    g_rowptr[MAX_N + 1];
__device__ int2   g_edge[MAX_E];     // (src_row, norm bits) sorted by dst col
__device__ float  g_Wt1[D * D];
__device__ float  g_Wt2[D * D];

// ---------------- f32x2 packed helpers (sm_103a) ----------------
__device__ __forceinline__ unsigned long long ffma2(unsigned long long a,
                                                    unsigned long long b,
                                                    unsigned long long c) {
    unsigned long long d;
    asm("fma.rn.f32x2 %0, %1, %2, %3;" : "=l"(d) : "l"(a), "l"(b), "l"(c));
    return d;
}
__device__ __forceinline__ unsigned long long pack2(float x, float y) {
    unsigned long long r;
    asm("mov.b64 %0, {%1, %2};" : "=l"(r) : "f"(x), "f"(y));
    return r;
}
__device__ __forceinline__ float2 unpack2(unsigned long long v) {
    float2 f;
    asm("mov.b64 {%0, %1}, %2;" : "=f"(f.x), "=f"(f.y) : "l"(v));
    return f;
}

// ---------------- init: zero deg/cnt/cnt2 ----------------
__global__ void init_kernel(int n) {
    int i = blockIdx.x * blockDim.x + threadIdx.x;
    if (i < n) {
        g_deg[i] = 0.f;
        g_cnt[i] = 0;
        g_cnt2[i] = 0;
    }
}

// ---------------- W transpose: Wt[k][c] = W[c][k]  (z selects which W) ----------------
__global__ void transpose_kernel(const float* __restrict__ A0, const float* __restrict__ A1,
                                 float* __restrict__ At0, float* __restrict__ At1) {
    __shared__ float tile[32][33];
    const float* A = blockIdx.z ? A1 : A0;
    float* At = blockIdx.z ? At1 : At0;
    int x = blockIdx.x * 32 + threadIdx.x;
    int y = blockIdx.y * 32 + threadIdx.y;
    #pragma unroll
    for (int i = 0; i < 32; i += 8)
        tile[threadIdx.y + i][threadIdx.x] = A[(y + i) * D + x];
    __syncthreads();
    x = blockIdx.y * 32 + threadIdx.x;
    y = blockIdx.x * 32 + threadIdx.y;
    #pragma unroll
    for (int i = 0; i < 32; i += 8)
        At[(y + i) * D + x] = tile[threadIdx.x][threadIdx.y + i];
}

// ---------------- CSR build ----------------
__global__ void hist_kernel(const float* __restrict__ w, const int* __restrict__ row,
                            const int* __restrict__ col, int E) {
    int e = blockIdx.x * blockDim.x + threadIdx.x;
    if (e < E) {
        atomicAdd(&g_deg[row[e]], w[e]);
        atomicAdd(&g_cnt[col[e]], 1);
    }
}

// single-block: dis = rsqrt(deg) + exclusive scan of g_cnt -> g_rowptr
__global__ void scan_kernel(int n, int E) {
    __shared__ int sa[1024];
    __shared__ int sb[1024];
    int t = threadIdx.x;
    int C = (n + 1023) >> 10;
    int base = t * C;
    int s = 0;
    for (int i = 0; i < C; i++) {
        int idx = base + i;
        if (idx < n) {
            s += g_cnt[idx];
            g_dis[idx] = rsqrtf(g_deg[idx]);
        }
    }
    sa[t] = s;
    __syncthreads();
    int* src = sa;
    int* dst = sb;
    for (int off = 1; off < 1024; off <<= 1) {
        int v = src[t];
        if (t >= off) v += src[t - off];
        dst[t] = v;
        __syncthreads();
        int* tmp = src; src = dst; dst = tmp;
    }
    int run = src[t] - s;  // exclusive offset for this chunk
    for (int i = 0; i < C; i++) {
        int idx = base + i;
        if (idx < n) {
            g_rowptr[idx] = run;
            run += g_cnt[idx];
        }
    }
    if (t == 0) g_rowptr[n] = E;
}

__global__ void fill_kernel(const float* __restrict__ w, const int* __restrict__ row,
                            const int* __restrict__ col, int E) {
    int e = blockIdx.x * blockDim.x + threadIdx.x;
    if (e < E) {
        int c = col[e];
        int r = row[e];
        int pos = atomicAdd(&g_cnt2[c], 1);
        float nm = g_dis[r] * w[e] * g_dis[c];
        g_edge[g_rowptr[c] + pos] = make_int2(r, __float_as_int(nm));
    }
}

// ---------------- GEMM: out = X @ W^T + b (Wt pre-transposed, read via L1) ----------------
// block = 256 threads, 64 rows per block, 8 rows x 4 cols per thread, f32x2 FMA.
// HALF_OUT: store output rows as fp16 (for gather consumption).
#define XT_S 72

struct h4 { __half2 a, b; };

template <bool RELU_IN, bool HALF_OUT>
__global__ __launch_bounds__(256, 4) void gemm_kernel(const float* __restrict__ X,
                                                      const float* __restrict__ Wt,
                                                      const float* __restrict__ bias,
                                                      void* __restrict__ out_, int n) {
    __shared__ float xsT[D * XT_S];  // 36.9 KB

    int tid = threadIdx.x;
    int row0 = blockIdx.x * 64;
    for (int i = tid; i < 64 * D; i += 256) {
        int r = i >> 7, k = i & 127;
        int gr = row0 + r;
        float v = (gr < n) ? X[(size_t)gr * D + k] : 0.f;
        if (RELU_IN) v = fmaxf(v, 0.f);
        xsT[k * XT_S + r] = v;
    }
    __syncthreads();

    int tx = tid & 31;   // cols 4*tx .. 4*tx+3
    int ty = tid >> 5;   // rows row0 + 8*ty .. +7 (4 packed row-pairs)
    unsigned long long acc[4][4];
    #pragma unroll
    for (int p = 0; p < 4; p++)
        #pragma unroll
        for (int j = 0; j < 4; j++) acc[p][j] = 0ull;

    const float* xbase = &xsT[8 * ty];
    const float4* wbase = (const float4*)(Wt) + tx;  // Wt[k*128 + 4*tx]

    #pragma unroll 4
    for (int k = 0; k < D; k++) {
        ulonglong2 a01 = *(const ulonglong2*)(xbase + k * XT_S);      // rows 0-3
        ulonglong2 a23 = *(const ulonglong2*)(xbase + k * XT_S + 4);  // rows 4-7
        float4 bv = __ldg(wbase + k * 32);
        unsigned long long b0 = pack2(bv.x, bv.x);
        unsigned long long b1 = pack2(bv.y, bv.y);
        unsigned long long b2 = pack2(bv.z, bv.z);
        unsigned long long b3 = pack2(bv.w, bv.w);

        acc[0][0] = ffma2(a01.x, b0, acc[0][0]);
        acc[0][1] = ffma2(a01.x, b1, acc[0][1]);
        acc[0][2] = ffma2(a01.x, b2, acc[0][2]);
        acc[0][3] = ffma2(a01.x, b3, acc[0][3]);
        acc[1][0] = ffma2(a01.y, b0, acc[1][0]);
        acc[1][1] = ffma2(a01.y, b1, acc[1][1]);
        acc[1][2] = ffma2(a01.y, b2, acc[1][2]);
        acc[1][3] = ffma2(a01.y, b3, acc[1][3]);
        acc[2][0] = ffma2(a23.x, b0, acc[2][0]);
        acc[2][1] = ffma2(a23.x, b1, acc[2][1]);
        acc[2][2] = ffma2(a23.x, b2, acc[2][2]);
        acc[2][3] = ffma2(a23.x, b3, acc[2][3]);
        acc[3][0] = ffma2(a23.y, b0, acc[3][0]);
        acc[3][1] = ffma2(a23.y, b1, acc[3][1]);
        acc[3][2] = ffma2(a23.y, b2, acc[3][2]);
        acc[3][3] = ffma2(a23.y, b3, acc[3][3]);
    }

    float4 bb = *(const float4*)&bias[4 * tx];
    #pragma unroll
    for (int p = 0; p < 4; p++) {
        float2 c0 = unpack2(acc[p][0]);
        float2 c1 = unpack2(acc[p][1]);
        float2 c2 = unpack2(acc[p][2]);
        float2 c3 = unpack2(acc[p][3]);
        int gr0 = row0 + 8 * ty + 2 * p;
        #pragma unroll
        for (int q = 0; q < 2; q++) {
            int gr = gr0 + q;
            if (gr >= n) break;
            float o0 = (q ? c0.y : c0.x) + bb.x;
            float o1 = (q ? c1.y : c1.x) + bb.y;
            float o2 = (q ? c2.y : c2.x) + bb.z;
            float o3 = (q ? c3.y : c3.x) + bb.w;
            if (HALF_OUT) {
                h4 hv;
                hv.a = __floats2half2_rn(o0, o1);
                hv.b = __floats2half2_rn(o2, o3);
                *(h4*)((__half*)out_ + (size_t)gr * D + 4 * tx) = hv;
            } else {
                *(float4*)((float*)out_ + (size_t)gr * D + 4 * tx) = make_float4(o0, o1, o2, o3);
            }
        }
    }
}

// ---------------- gather: out[c] = sum_{e in CSR[c]} norm[e] * h[row[e]] ----------------
// h is fp16 (256B/row); warp per node; lane covers cols 4*lane..4*lane+3; unroll 4.
__device__ __forceinline__ void gacc(float4& a, float nm, uint2 u) {
    float2 f0 = __half22float2(*(__half2*)&u.x);
    float2 f1 = __half22float2(*(__half2*)&u.y);
    a.x += nm * f0.x; a.y += nm * f0.y; a.z += nm * f1.x; a.w += nm * f1.y;
}

__global__ void gather_kernel(const uint2* __restrict__ h, float* __restrict__ out, int n) {
    int warp = (blockIdx.x * blockDim.x + threadIdx.x) >> 5;
    int lane = threadIdx.x & 31;
    if (warp >= n) return;
    int start = g_rowptr[warp];
    int end = g_rowptr[warp + 1];
    float4 a0 = make_float4(0.f, 0.f, 0.f, 0.f);
    float4 a1 = make_float4(0.f, 0.f, 0.f, 0.f);
    float4 a2 = make_float4(0.f, 0.f, 0.f, 0.f);
    float4 a3 = make_float4(0.f, 0.f, 0.f, 0.f);
    int j = start;
    for (; j + 4 <= end; j += 4) {
        int2 e0 = g_edge[j];
        int2 e1 = g_edge[j + 1];
        int2 e2 = g_edge[j + 2];
        int2 e3 = g_edge[j + 3];
        uint2 u0 = __ldg(&h[(size_t)e0.x * 32 + lane]);
        uint2 u1 = __ldg(&h[(size_t)e1.x * 32 + lane]);
        uint2 u2 = __ldg(&h[(size_t)e2.x * 32 + lane]);
        uint2 u3 = __ldg(&h[(size_t)e3.x * 32 + lane]);
        gacc(a0, __int_as_float(e0.y), u0);
        gacc(a1, __int_as_float(e1.y), u1);
        gacc(a2, __int_as_float(e2.y), u2);
        gacc(a3, __int_as_float(e3.y), u3);
    }
    for (; j < end; j++) {
        int2 e0 = g_edge[j];
        uint2 u0 = __ldg(&h[(size_t)e0.x * 32 + lane]);
        gacc(a0, __int_as_float(e0.y), u0);
    }
    float4 r = make_float4(a0.x + a1.x + a2.x + a3.x,
                           a0.y + a1.y + a2.y + a3.y,
                           a0.z + a1.z + a2.z + a3.z,
                           a0.w + a1.w + a2.w + a3.w);
    *(float4*)&out[(size_t)warp * D + lane * 4] = r;
}

extern "C" void kernel_launch(void* const* d_in, const int* in_sizes, int n_in,
                              void* d_out, int out_size) {
    const float* x  = (const float*)d_in[0];
    const int*   ei = (const int*)d_in[1];
    const float* ew = (const float*)d_in[2];
    const float* W1 = (const float*)d_in[3];
    const float* b1 = (const float*)d_in[4];
    const float* W2 = (const float*)d_in[5];
    const float* b2 = (const float*)d_in[6];
    float* out = (float*)d_out;

    int n = in_sizes[0] / D;
    int E = in_sizes[2];
    const int* row = ei;
    const int* col = ei + E;

    void *p_h1, *p_agg1, *p_h2, *p_Wt1, *p_Wt2;
    cudaGetSymbolAddress(&p_h1, g_h1);
    cudaGetSymbolAddress(&p_agg1, g_agg1);
    cudaGetSymbolAddress(&p_h2, g_h2);
    cudaGetSymbolAddress(&p_Wt1, g_Wt1);
    cudaGetSymbolAddress(&p_Wt2, g_Wt2);

    // prep: init + transposes + CSR build
    init_kernel<<<(n + 255) / 256, 256>>>(n);
    transpose_kernel<<<dim3(4, 4, 2), dim3(32, 8)>>>(W1, W2, (float*)p_Wt1, (float*)p_Wt2);
    hist_kernel<<<(E + 255) / 256, 256>>>(ew, row, col, E);
    scan_kernel<<<1, 1024>>>(n, E);
    fill_kernel<<<(E + 255) / 256, 256>>>(ew, row, col, E);

    int gemm_blocks = (n + 63) / 64;
    int gather_blocks = (n * 32 + 255) / 256;

    // layer 1 (GEMM -> fp16 h1, gather -> fp32 agg1)
    gemm_kernel<false, true><<<gemm_blocks, 256>>>(x, (const float*)p_Wt1, b1, p_h1, n);
    gather_kernel<<<gather_blocks, 256>>>((const uint2*)p_h1, (float*)p_agg1, n);

    // layer 2 (relu fused into GEMM input load; GEMM -> fp16 h2, gather -> fp32 out)
    gemm_kernel<true, true><<<gemm_blocks, 256>>>((const float*)p_agg1, (const float*)p_Wt2, b2, p_h2, n);
    gather_kernel<<<gather_blocks, 256>>>((const uint2*)p_h2, out, n);
}

// round 8
// speedup vs baseline: 1.5615x; 1.5615x over previous
#include <cuda_runtime.h>
#include <cuda_fp16.h>
#include <cuda_bf16.h>

#define MAX_N 50000
#define MAX_E 600000
#define D 128
#define NB_MAX 1024   // max scan blocks supported

// scratch (no allocation allowed -> __device__ globals)
__device__ __half g_h1[MAX_N * D];
__device__ float  g_agg1[MAX_N * D];
__device__ __half g_h2[MAX_N * D];
__device__ float  g_deg[MAX_N];
__device__ float  g_dis[MAX_N];
__device__ int    g_cnt[MAX_N];
__device__ int    g_cnt2[MAX_N];
__device__ int    g_rowptr[MAX_N + 1];
__device__ int    g_bsum[NB_MAX];
__device__ int    g_boff[NB_MAX];
__device__ int2   g_edge[MAX_E];     // (src_row, norm bits) sorted by dst col
__device__ float  g_Wt1[D * D];
__device__ float  g_Wt2[D * D];

// ---------------- f32x2 packed helpers (sm_103a) ----------------
__device__ __forceinline__ unsigned long long ffma2(unsigned long long a,
                                                    unsigned long long b,
                                                    unsigned long long c) {
    unsigned long long d;
    asm("fma.rn.f32x2 %0, %1, %2, %3;" : "=l"(d) : "l"(a), "l"(b), "l"(c));
    return d;
}
__device__ __forceinline__ unsigned long long pack2(float x, float y) {
    unsigned long long r;
    asm("mov.b64 %0, {%1, %2};" : "=l"(r) : "f"(x), "f"(y));
    return r;
}
__device__ __forceinline__ float2 unpack2(unsigned long long v) {
    float2 f;
    asm("mov.b64 {%0, %1}, %2;" : "=f"(f.x), "=f"(f.y) : "l"(v));
    return f;
}

// ---------------- init: zero deg/cnt/cnt2 ----------------
__global__ void init_kernel(int n) {
    int i = blockIdx.x * blockDim.x + threadIdx.x;
    if (i < n) {
        g_deg[i] = 0.f;
        g_cnt[i] = 0;
        g_cnt2[i] = 0;
    }
}

// ---------------- W transpose: Wt[k][c] = W[c][k]  (z selects which W) ----------------
__global__ void transpose_kernel(const float* __restrict__ A0, const float* __restrict__ A1,
                                 float* __restrict__ At0, float* __restrict__ At1) {
    __shared__ float tile[32][33];
    const float* A = blockIdx.z ? A1 : A0;
    float* At = blockIdx.z ? At1 : At0;
    int x = blockIdx.x * 32 + threadIdx.x;
    int y = blockIdx.y * 32 + threadIdx.y;
    #pragma unroll
    for (int i = 0; i < 32; i += 8)
        tile[threadIdx.y + i][threadIdx.x] = A[(y + i) * D + x];
    __syncthreads();
    x = blockIdx.y * 32 + threadIdx.x;
    y = blockIdx.x * 32 + threadIdx.y;
    #pragma unroll
    for (int i = 0; i < 32; i += 8)
        At[(y + i) * D + x] = tile[threadIdx.x][threadIdx.y + i];
}

// ---------------- CSR build ----------------
__global__ void hist_kernel(const float* __restrict__ w, const int* __restrict__ row,
                            const int* __restrict__ col, int E) {
    int e = blockIdx.x * blockDim.x + threadIdx.x;
    if (e < E) {
        atomicAdd(&g_deg[row[e]], w[e]);
        atomicAdd(&g_cnt[col[e]], 1);
    }
}

// pass 1: per-block sum of cnt, plus dis = rsqrt(deg) (parallel)
__global__ void bsum_kernel(int n) {
    __shared__ int ws[8];
    int i = blockIdx.x * 256 + threadIdx.x;
    int c = (i < n) ? g_cnt[i] : 0;
    if (i < n) g_dis[i] = rsqrtf(g_deg[i]);
    // warp reduce
    int v = c;
    #pragma unroll
    for (int o = 16; o > 0; o >>= 1) v += __shfl_down_sync(0xffffffff, v, o);
    if ((threadIdx.x & 31) == 0) ws[threadIdx.x >> 5] = v;
    __syncthreads();
    if (threadIdx.x < 8) {
        int s = ws[threadIdx.x];
        #pragma unroll
        for (int o = 4; o > 0; o >>= 1) s += __shfl_down_sync(0xff, s, o);
        if (threadIdx.x == 0) g_bsum[blockIdx.x] = s;
    }
}

// pass 2: exclusive scan of block sums (single small block)
__global__ void bscan_kernel(int nb) {
    __shared__ int sa[NB_MAX];
    __shared__ int sb[NB_MAX];
    int t = threadIdx.x;
    #pragma unroll
    for (int i = t; i < NB_MAX; i += 1024) sa[i] = (i < nb) ? g_bsum[i] : 0;
    __syncthreads();
    int* src = sa;
    int* dst = sb;
    for (int off = 1; off < NB_MAX; off <<= 1) {
        for (int i = t; i < NB_MAX; i += 1024) {
            int v = src[i];
            if (i >= off) v += src[i - off];
            dst[i] = v;
        }
        __syncthreads();
        int* tmp = src; src = dst; dst = tmp;
    }
    for (int i = t; i < nb; i += 1024)
        g_boff[i] = (i == 0) ? 0 : src[i - 1];  // exclusive
}

// pass 3: block-local exclusive scan + block offset -> rowptr
__global__ void rowptr_kernel(int n, int E) {
    __shared__ int sa[256];
    __shared__ int sb[256];
    int t = threadIdx.x;
    int i = blockIdx.x * 256 + t;
    int c = (i < n) ? g_cnt[i] : 0;
    sa[t] = c;
    __syncthreads();
    int* src = sa;
    int* dst = sb;
    #pragma unroll
    for (int off = 1; off < 256; off <<= 1) {
        int v = src[t];
        if (t >= off) v += src[t - off];
        dst[t] = v;
        __syncthreads();
        int* tmp = src; src = dst; dst = tmp;
    }
    if (i < n) g_rowptr[i] = g_boff[blockIdx.x] + src[t] - c;  // exclusive
    if (blockIdx.x == 0 && t == 0) g_rowptr[n] = E;
}

__global__ void fill_kernel(const float* __restrict__ w, const int* __restrict__ row,
                            const int* __restrict__ col, int E) {
    int e = blockIdx.x * blockDim.x + threadIdx.x;
    if (e < E) {
        int c = col[e];
        int r = row[e];
        int pos = atomicAdd(&g_cnt2[c], 1);
        float nm = g_dis[r] * w[e] * g_dis[c];
        g_edge[g_rowptr[c] + pos] = make_int2(r, __float_as_int(nm));
    }
}

// ---------------- GEMM: out = X @ W^T + b (Wt pre-transposed, read via L1) ----------------
// block = 256 threads, 64 rows per block, 8 rows x 4 cols per thread, f32x2 FMA.
// HALF_OUT: store output rows as fp16 (for gather consumption).
#define XT_S 72

struct h4 { __half2 a, b; };

template <bool RELU_IN, bool HALF_OUT>
__global__ __launch_bounds__(256, 4) void gemm_kernel(const float* __restrict__ X,
                                                      const float* __restrict__ Wt,
                                                      const float* __restrict__ bias,
                                                      void* __restrict__ out_, int n) {
    __shared__ float xsT[D * XT_S];  // 36.9 KB

    int tid = threadIdx.x;
    int row0 = blockIdx.x * 64;
    for (int i = tid; i < 64 * D; i += 256) {
        int r = i >> 7, k = i & 127;
        int gr = row0 + r;
        float v = (gr < n) ? X[(size_t)gr * D + k] : 0.f;
        if (RELU_IN) v = fmaxf(v, 0.f);
        xsT[k * XT_S + r] = v;
    }
    __syncthreads();

    int tx = tid & 31;   // cols 4*tx .. 4*tx+3
    int ty = tid >> 5;   // rows row0 + 8*ty .. +7 (4 packed row-pairs)
    unsigned long long acc[4][4];
    #pragma unroll
    for (int p = 0; p < 4; p++)
        #pragma unroll
        for (int j = 0; j < 4; j++) acc[p][j] = 0ull;

    const float* xbase = &xsT[8 * ty];
    const float4* wbase = (const float4*)(Wt) + tx;  // Wt[k*128 + 4*tx]

    #pragma unroll 4
    for (int k = 0; k < D; k++) {
        ulonglong2 a01 = *(const ulonglong2*)(xbase + k * XT_S);      // rows 0-3
        ulonglong2 a23 = *(const ulonglong2*)(xbase + k * XT_S + 4);  // rows 4-7
        float4 bv = __ldg(wbase + k * 32);
        unsigned long long b0 = pack2(bv.x, bv.x);
        unsigned long long b1 = pack2(bv.y, bv.y);
        unsigned long long b2 = pack2(bv.z, bv.z);
        unsigned long long b3 = pack2(bv.w, bv.w);

        acc[0][0] = ffma2(a01.x, b0, acc[0][0]);
        acc[0][1] = ffma2(a01.x, b1, acc[0][1]);
        acc[0][2] = ffma2(a01.x, b2, acc[0][2]);
        acc[0][3] = ffma2(a01.x, b3, acc[0][3]);
        acc[1][0] = ffma2(a01.y, b0, acc[1][0]);
        acc[1][1] = ffma2(a01.y, b1, acc[1][1]);
        acc[1][2] = ffma2(a01.y, b2, acc[1][2]);
        acc[1][3] = ffma2(a01.y, b3, acc[1][3]);
        acc[2][0] = ffma2(a23.x, b0, acc[2][0]);
        acc[2][1] = ffma2(a23.x, b1, acc[2][1]);
        acc[2][2] = ffma2(a23.x, b2, acc[2][2]);
        acc[2][3] = ffma2(a23.x, b3, acc[2][3]);
        acc[3][0] = ffma2(a23.y, b0, acc[3][0]);
        acc[3][1] = ffma2(a23.y, b1, acc[3][1]);
        acc[3][2] = ffma2(a23.y, b2, acc[3][2]);
        acc[3][3] = ffma2(a23.y, b3, acc[3][3]);
    }

    float4 bb = *(const float4*)&bias[4 * tx];
    #pragma unroll
    for (int p = 0; p < 4; p++) {
        float2 c0 = unpack2(acc[p][0]);
        float2 c1 = unpack2(acc[p][1]);
        float2 c2 = unpack2(acc[p][2]);
        float2 c3 = unpack2(acc[p][3]);
        int gr0 = row0 + 8 * ty + 2 * p;
        #pragma unroll
        for (int q = 0; q < 2; q++) {
            int gr = gr0 + q;
            if (gr >= n) break;
            float o0 = (q ? c0.y : c0.x) + bb.x;
            float o1 = (q ? c1.y : c1.x) + bb.y;
            float o2 = (q ? c2.y : c2.x) + bb.z;
            float o3 = (q ? c3.y : c3.x) + bb.w;
            if (HALF_OUT) {
                h4 hv;
                hv.a = __floats2half2_rn(o0, o1);
                hv.b = __floats2half2_rn(o2, o3);
                *(h4*)((__half*)out_ + (size_t)gr * D + 4 * tx) = hv;
            } else {
                *(float4*)((float*)out_ + (size_t)gr * D + 4 * tx) = make_float4(o0, o1, o2, o3);
            }
        }
    }
}

// ---------------- gather: out[c] = sum_{e in CSR[c]} norm[e] * h[row[e]] ----------------
// h is fp16 (256B/row); warp per node; lane covers cols 4*lane..4*lane+3; unroll 4.
__device__ __forceinline__ void gacc(float4& a, float nm, uint2 u) {
    float2 f0 = __half22float2(*(__half2*)&u.x);
    float2 f1 = __half22float2(*(__half2*)&u.y);
    a.x += nm * f0.x; a.y += nm * f0.y; a.z += nm * f1.x; a.w += nm * f1.y;
}

__global__ void gather_kernel(const uint2* __restrict__ h, float* __restrict__ out, int n) {
    int warp = (blockIdx.x * blockDim.x + threadIdx.x) >> 5;
    int lane = threadIdx.x & 31;
    if (warp >= n) return;
    int start = g_rowptr[warp];
    int end = g_rowptr[warp + 1];
    float4 a0 = make_float4(0.f, 0.f, 0.f, 0.f);
    float4 a1 = make_float4(0.f, 0.f, 0.f, 0.f);
    float4 a2 = make_float4(0.f, 0.f, 0.f, 0.f);
    float4 a3 = make_float4(0.f, 0.f, 0.f, 0.f);
    int j = start;
    for (; j + 4 <= end; j += 4) {
        int2 e0 = g_edge[j];
        int2 e1 = g_edge[j + 1];
        int2 e2 = g_edge[j + 2];
        int2 e3 = g_edge[j + 3];
        uint2 u0 = __ldg(&h[(size_t)e0.x * 32 + lane]);
        uint2 u1 = __ldg(&h[(size_t)e1.x * 32 + lane]);
        uint2 u2 = __ldg(&h[(size_t)e2.x * 32 + lane]);
        uint2 u3 = __ldg(&h[(size_t)e3.x * 32 + lane]);
        gacc(a0, __int_as_float(e0.y), u0);
        gacc(a1, __int_as_float(e1.y), u1);
        gacc(a2, __int_as_float(e2.y), u2);
        gacc(a3, __int_as_float(e3.y), u3);
    }
    for (; j < end; j++) {
        int2 e0 = g_edge[j];
        uint2 u0 = __ldg(&h[(size_t)e0.x * 32 + lane]);
        gacc(a0, __int_as_float(e0.y), u0);
    }
    float4 r = make_float4(a0.x + a1.x + a2.x + a3.x,
                           a0.y + a1.y + a2.y + a3.y,
                           a0.z + a1.z + a2.z + a3.z,
                           a0.w + a1.w + a2.w + a3.w);
    *(float4*)&out[(size_t)warp * D + lane * 4] = r;
}

extern "C" void kernel_launch(void* const* d_in, const int* in_sizes, int n_in,
                              void* d_out, int out_size) {
    const float* x  = (const float*)d_in[0];
    const int*   ei = (const int*)d_in[1];
    const float* ew = (const float*)d_in[2];
    const float* W1 = (const float*)d_in[3];
    const float* b1 = (const float*)d_in[4];
    const float* W2 = (const float*)d_in[5];
    const float* b2 = (const float*)d_in[6];
    float* out = (float*)d_out;

    int n = in_sizes[0] / D;
    int E = in_sizes[2];
    const int* row = ei;
    const int* col = ei + E;

    void *p_h1, *p_agg1, *p_h2, *p_Wt1, *p_Wt2;
    cudaGetSymbolAddress(&p_h1, g_h1);
    cudaGetSymbolAddress(&p_agg1, g_agg1);
    cudaGetSymbolAddress(&p_h2, g_h2);
    cudaGetSymbolAddress(&p_Wt1, g_Wt1);
    cudaGetSymbolAddress(&p_Wt2, g_Wt2);

    int nb = (n + 255) / 256;  // scan blocks (196 for n=50000, <= NB_MAX)

    // prep: init + transposes + CSR build (parallel scan)
    init_kernel<<<(n + 255) / 256, 256>>>(n);
    transpose_kernel<<<dim3(4, 4, 2), dim3(32, 8)>>>(W1, W2, (float*)p_Wt1, (float*)p_Wt2);
    hist_kernel<<<(E + 255) / 256, 256>>>(ew, row, col, E);
    bsum_kernel<<<nb, 256>>>(n);
    bscan_kernel<<<1, 1024>>>(nb);
    rowptr_kernel<<<nb, 256>>>(n, E);
    fill_kernel<<<(E + 255) / 256, 256>>>(ew, row, col, E);

    int gemm_blocks = (n + 63) / 64;
    int gather_blocks = (n * 32 + 255) / 256;

    // layer 1 (GEMM -> fp16 h1, gather -> fp32 agg1)
    gemm_kernel<false, true><<<gemm_blocks, 256>>>(x, (const float*)p_Wt1, b1, p_h1, n);
    gather_kernel<<<gather_blocks, 256>>>((const uint2*)p_h1, (float*)p_agg1, n);

    // layer 2 (relu fused into GEMM input load; GEMM -> fp16 h2, gather -> fp32 out)
    gemm_kernel<true, true><<<gemm_blocks, 256>>>((const float*)p_agg1, (const float*)p_Wt2, b2, p_h2, n);
    gather_kernel<<<gather_blocks, 256>>>((const uint2*)p_h2, out, n);
}